// round 13
// baseline (speedup 1.0000x reference)
#include <cuda_runtime.h>
#include <cuda_bf16.h>
#include <cuda_fp16.h>
#include <cstdint>

#define D 128
#define MAX_NODES 100000
#define MAX_EDGES 1600000

// ---- scratch (__device__ globals; no allocs allowed) ----
__device__ uint2  g_egoh[MAX_NODES * 32];        // ego as fp16 (4 halves/lane), 25.6 MB
__device__ uint2  g_edges[MAX_EDGES];            // per-node {src, w-bits}, 12.8 MB
__device__ int    g_counts[MAX_NODES];
__device__ int    g_offsets[MAX_NODES];
__device__ int    g_cursor[MAX_NODES];
__device__ int    g_total;
__device__ int    g_idx_is32;

// ---------------------------------------------------------------------------
// K1: fused prep: detect idx dtype + zero counts + convert ego -> fp16.
// All independent; grid-stride over n4 = n_nodes*32 (covers n_nodes zeroing).
// dtype rule: int64 indices < 1e5 have zero high word; any nonzero high word
// in 64 samples => buffer is int32 pairs.
// ---------------------------------------------------------------------------
__global__ void prep_kernel(const float4* __restrict__ ego4,
                            const unsigned long long* __restrict__ ei,
                            int n_nodes, int n4, int n_samples) {
    int i = blockIdx.x * blockDim.x + threadIdx.x;
    if (i == 0) {
        int saw_high = 0;
        for (int s = 0; s < n_samples; s++)
            if (ei[s] >> 32) { saw_high = 1; break; }
        g_idx_is32 = saw_high;
        g_total = 0;
    }
    if (i < n_nodes) g_counts[i] = 0;
    if (i < n4) {
        float4 v = ego4[i];
        __half2 h01 = __floats2half2_rn(v.x, v.y);
        __half2 h23 = __floats2half2_rn(v.z, v.w);
        g_egoh[i] = make_uint2(*reinterpret_cast<unsigned*>(&h01),
                               *reinterpret_cast<unsigned*>(&h23));
    }
}

// K2: histogram of dst degrees
__global__ void count_kernel(const void* __restrict__ ei, int n_edges, int n_nodes) {
    int e = blockIdx.x * blockDim.x + threadIdx.x;
    if (e >= n_edges) return;
    long long dst = g_idx_is32 ? (long long)((const int*)ei)[e]
                               : ((const long long*)ei)[e];
    if ((unsigned long long)dst < (unsigned long long)n_nodes)
        atomicAdd(&g_counts[dst], 1);
}

// K3: per-node segment offsets. Block-local scan + one global atomicAdd per
// block for the base (segment disjointness is order-independent).
__global__ void offsets_kernel(int n_nodes) {
    __shared__ int warp_sums[32];
    __shared__ int block_base;
    int i = blockIdx.x * 1024 + threadIdx.x;
    int lane = threadIdx.x & 31, wid = threadIdx.x >> 5;

    int c = (i < n_nodes) ? g_counts[i] : 0;
    int x = c;
    #pragma unroll
    for (int d = 1; d < 32; d <<= 1) {
        int y = __shfl_up_sync(0xFFFFFFFFu, x, d);
        if (lane >= d) x += y;
    }
    if (lane == 31) warp_sums[wid] = x;
    __syncthreads();
    if (wid == 0) {
        int s = warp_sums[lane];
        #pragma unroll
        for (int d = 1; d < 32; d <<= 1) {
            int y = __shfl_up_sync(0xFFFFFFFFu, s, d);
            if (lane >= d) s += y;
        }
        warp_sums[lane] = s;
        if (lane == 31) block_base = atomicAdd(&g_total, s);
    }
    __syncthreads();
    int warp_base = (wid > 0) ? warp_sums[wid - 1] : 0;
    int excl = block_base + warp_base + (x - c);
    if (i < n_nodes) { g_offsets[i] = excl; g_cursor[i] = excl; }
}

// K4: scatter edges into per-node segments
__global__ void fill_kernel(const void* __restrict__ ei,
                            const float* __restrict__ ew,
                            int n_edges, int n_nodes) {
    int e = blockIdx.x * blockDim.x + threadIdx.x;
    if (e >= n_edges) return;
    long long dst, src;
    if (g_idx_is32) {
        dst = (long long)((const int*)ei)[e];
        src = (long long)((const int*)ei)[n_edges + e];
    } else {
        dst = ((const long long*)ei)[e];
        src = ((const long long*)ei)[n_edges + e];
    }
    if ((unsigned long long)dst >= (unsigned long long)n_nodes ||
        (unsigned long long)src >= (unsigned long long)n_nodes) return;
    int pos = atomicAdd(&g_cursor[dst], 1);
    if (pos < MAX_EDGES)
        g_edges[pos] = make_uint2((unsigned)src, __float_as_uint(ew[e]));
}

// ---------------------------------------------------------------------------
// K5: FUSED persistent aggregate + bf16 tensor GEMM.
// Per 64-row tile: 8 warps aggregate 8 nodes each (fp16 messages, fp32 acc,
// fp32 self row), hi/lo bf16 split straight into smem; then the 3-pass
// m16n8k16 GEMM + bias + LeakyReLU. W fragment table staged once per CTA.
// ---------------------------------------------------------------------------
#define XS_STRIDE 68   // u32 (k-pair) stride: bank = 4*row + pair -> conflict-free

__device__ __forceinline__ unsigned pack_bf16(float a, float b) {
    __nv_bfloat162 t = __floats2bfloat162_rn(a, b);
    return *reinterpret_cast<unsigned*>(&t);
}

__device__ __forceinline__ void acc_h(float4& acc, uint2 q, float w) {
    float2 f01 = __half22float2(*reinterpret_cast<__half2*>(&q.x));
    float2 f23 = __half22float2(*reinterpret_cast<__half2*>(&q.y));
    acc.x += f01.x * w; acc.y += f01.y * w;
    acc.z += f23.x * w; acc.w += f23.y * w;
}

__device__ __forceinline__ void mma_bf16(float* c, const unsigned* a,
                                         unsigned b0, unsigned b1) {
    asm volatile(
        "mma.sync.aligned.m16n8k16.row.col.f32.bf16.bf16.f32 "
        "{%0,%1,%2,%3}, {%4,%5,%6,%7}, {%8,%9}, {%0,%1,%2,%3};"
        : "+f"(c[0]), "+f"(c[1]), "+f"(c[2]), "+f"(c[3])
        : "r"(a[0]), "r"(a[1]), "r"(a[2]), "r"(a[3]), "r"(b0), "r"(b1));
}

__global__ __launch_bounds__(256, 2)
void fused_agg_gemm_kernel(const float4* __restrict__ ego4,
                           const float* __restrict__ W,
                           const float* __restrict__ b,
                           float* __restrict__ out, int n_nodes, int n_tiles) {
    extern __shared__ unsigned smu[];
    uint4*    wf    = reinterpret_cast<uint4*>(smu);       // [16 t][8 kt][32 l] {hi01,hi89,lo01,lo89}
    unsigned* xs_hi = smu + 16384;                         // [64][XS_STRIDE]
    unsigned* xs_lo = xs_hi + 64 * XS_STRIDE;
    float*    bs    = reinterpret_cast<float*>(xs_lo + 64 * XS_STRIDE);  // [128]

    int tid = threadIdx.x;
    int lane = tid & 31, wid = tid >> 5;

    // ---- stage W fragments once per CTA ----
    for (int e = tid; e < 4096; e += 256) {
        int t = e >> 8, kt = (e >> 5) & 7, l = e & 31;
        int n = t * 8 + (l >> 2);
        int k0 = kt * 16 + (l & 3) * 2;
        const float* wr = W + n * D + k0;
        float f0 = wr[0], f1 = wr[1], f8 = wr[8], f9 = wr[9];
        __nv_bfloat162 h01 = __floats2bfloat162_rn(f0, f1);
        __nv_bfloat162 h89 = __floats2bfloat162_rn(f8, f9);
        unsigned hi01 = *reinterpret_cast<unsigned*>(&h01);
        unsigned hi89 = *reinterpret_cast<unsigned*>(&h89);
        unsigned lo01 = pack_bf16(f0 - __bfloat162float(h01.x), f1 - __bfloat162float(h01.y));
        unsigned lo89 = pack_bf16(f8 - __bfloat162float(h89.x), f9 - __bfloat162float(h89.y));
        wf[e] = make_uint4(hi01, hi89, lo01, lo89);
    }
    if (tid < D) bs[tid] = b[tid];

    int m0 = (wid >> 1) * 16;
    int nh = (wid & 1) * 8;
    int g = lane >> 2, tig = lane & 3;

    for (int tile = blockIdx.x; tile < n_tiles; tile += gridDim.x) {
        int row0 = tile * 64;
        __syncthreads();   // previous iteration's readers done before overwrite

        // ---- aggregate phase: warp wid -> nodes row0 + wid*8 .. +7 ----
        #pragma unroll 1
        for (int i = 0; i < 8; i++) {
            int r = wid * 8 + i;
            int nid = row0 + r;
            float4 acc = make_float4(0.f, 0.f, 0.f, 0.f);
            if (nid < n_nodes) {
                acc = ego4[(long)nid * 32 + lane];   // self row, fp32
                int off = g_offsets[nid];
                int deg = g_counts[nid];
                int e = 0;
                for (; e + 4 <= deg; e += 4) {
                    uint2 p0 = g_edges[off + e + 0];
                    uint2 p1 = g_edges[off + e + 1];
                    uint2 p2 = g_edges[off + e + 2];
                    uint2 p3 = g_edges[off + e + 3];
                    uint2 q0 = g_egoh[(long)p0.x * 32 + lane];
                    uint2 q1 = g_egoh[(long)p1.x * 32 + lane];
                    uint2 q2 = g_egoh[(long)p2.x * 32 + lane];
                    uint2 q3 = g_egoh[(long)p3.x * 32 + lane];
                    acc_h(acc, q0, __uint_as_float(p0.y));
                    acc_h(acc, q1, __uint_as_float(p1.y));
                    acc_h(acc, q2, __uint_as_float(p2.y));
                    acc_h(acc, q3, __uint_as_float(p3.y));
                }
                for (; e < deg; e++) {
                    uint2 p = g_edges[off + e];
                    uint2 q = g_egoh[(long)p.x * 32 + lane];
                    acc_h(acc, q, __uint_as_float(p.y));
                }
            }
            // hi/lo bf16 split straight into smem (layout: pair p = k/2)
            __nv_bfloat162 h01 = __floats2bfloat162_rn(acc.x, acc.y);
            __nv_bfloat162 h23 = __floats2bfloat162_rn(acc.z, acc.w);
            xs_hi[r * XS_STRIDE + 2 * lane]     = *reinterpret_cast<unsigned*>(&h01);
            xs_hi[r * XS_STRIDE + 2 * lane + 1] = *reinterpret_cast<unsigned*>(&h23);
            xs_lo[r * XS_STRIDE + 2 * lane]     =
                pack_bf16(acc.x - __bfloat162float(h01.x), acc.y - __bfloat162float(h01.y));
            xs_lo[r * XS_STRIDE + 2 * lane + 1] =
                pack_bf16(acc.z - __bfloat162float(h23.x), acc.w - __bfloat162float(h23.y));
        }
        __syncthreads();

        // ---- GEMM phase ----
        float acc[8][4];
        #pragma unroll
        for (int t = 0; t < 8; t++)
            #pragma unroll
            for (int i = 0; i < 4; i++) acc[t][i] = 0.f;

        #pragma unroll
        for (int kt = 0; kt < 8; kt++) {
            int base = kt * 8 + tig;
            unsigned ahi[4], alo[4];
            ahi[0] = xs_hi[(m0 + g) * XS_STRIDE + base];
            ahi[1] = xs_hi[(m0 + g + 8) * XS_STRIDE + base];
            ahi[2] = xs_hi[(m0 + g) * XS_STRIDE + base + 4];
            ahi[3] = xs_hi[(m0 + g + 8) * XS_STRIDE + base + 4];
            alo[0] = xs_lo[(m0 + g) * XS_STRIDE + base];
            alo[1] = xs_lo[(m0 + g + 8) * XS_STRIDE + base];
            alo[2] = xs_lo[(m0 + g) * XS_STRIDE + base + 4];
            alo[3] = xs_lo[(m0 + g + 8) * XS_STRIDE + base + 4];

            #pragma unroll
            for (int t = 0; t < 8; t++) {
                uint4 w4 = wf[((nh + t) * 8 + kt) * 32 + lane];
                mma_bf16(acc[t], ahi, w4.x, w4.y);   // hi*hi
                mma_bf16(acc[t], ahi, w4.z, w4.w);   // hi*lo
                mma_bf16(acc[t], alo, w4.x, w4.y);   // lo*hi
            }
        }

        int r0 = row0 + m0 + g;
        #pragma unroll
        for (int t = 0; t < 8; t++) {
            int col = (nh + t) * 8 + 2 * tig;
            float bb0 = bs[col], bb1 = bs[col + 1];
            float v0 = acc[t][0] + bb0, v1 = acc[t][1] + bb1;
            float v2 = acc[t][2] + bb0, v3 = acc[t][3] + bb1;
            v0 = v0 > 0.f ? v0 : 0.01f * v0;
            v1 = v1 > 0.f ? v1 : 0.01f * v1;
            v2 = v2 > 0.f ? v2 : 0.01f * v2;
            v3 = v3 > 0.f ? v3 : 0.01f * v3;
            if (r0 < n_nodes)
                *reinterpret_cast<float2*>(out + (long)r0 * D + col) = make_float2(v0, v1);
            if (r0 + 8 < n_nodes)
                *reinterpret_cast<float2*>(out + (long)(r0 + 8) * D + col) = make_float2(v2, v3);
        }
    }
}

// ---------------------------------------------------------------------------
extern "C" void kernel_launch(void* const* d_in, const int* in_sizes, int n_in,
                              void* d_out, int out_size) {
    const float* ego = (const float*)d_in[0];
    const void*  ei  = d_in[1];
    const float* ew  = (const float*)d_in[2];
    const float* W   = (const float*)d_in[3];
    const float* b   = (const float*)d_in[4];
    float*       out = (float*)d_out;

    int n_nodes = in_sizes[0] / D;
    int n_edges = in_sizes[2];
    if (n_edges > MAX_EDGES) n_edges = MAX_EDGES;

    int n4 = n_nodes * 32;
    int n_samples = n_edges < 64 ? n_edges : 64;

    prep_kernel<<<(n4 + 255) / 256, 256>>>((const float4*)ego,
                                           (const unsigned long long*)ei,
                                           n_nodes, n4, n_samples);
    count_kernel<<<(n_edges + 255) / 256, 256>>>(ei, n_edges, n_nodes);
    offsets_kernel<<<(n_nodes + 1023) / 1024, 1024>>>(n_nodes);
    fill_kernel<<<(n_edges + 255) / 256, 256>>>(ei, ew, n_edges, n_nodes);

    int n_tiles = (n_nodes + 63) / 64;
    int gblocks = 296 < n_tiles ? 296 : n_tiles;
    size_t smem = (16384 + 2 * 64 * XS_STRIDE) * sizeof(unsigned) + D * sizeof(float);
    cudaFuncSetAttribute(fused_agg_gemm_kernel,
                         cudaFuncAttributeMaxDynamicSharedMemorySize, (int)smem);
    fused_agg_gemm_kernel<<<gblocks, 256, smem>>>((const float4*)ego, W, b, out,
                                                  n_nodes, n_tiles);
}

// round 14
// speedup vs baseline: 1.3361x; 1.3361x over previous
#include <cuda_runtime.h>
#include <cuda_bf16.h>
#include <cuda_fp16.h>
#include <cstdint>

#define D 128
#define MAX_NODES 100000
#define MAX_EDGES 1600000

// ---- scratch (__device__ globals; no allocs allowed) ----
__device__ uint2  g_xhi[MAX_NODES * 32];         // x hi bf16 pairs, 25.6 MB
__device__ uint2  g_xlo[MAX_NODES * 32];         // x lo bf16 pairs, 25.6 MB
__device__ uint2  g_egoh[MAX_NODES * 32];        // ego as fp16, 25.6 MB
__device__ uint2  g_edges[MAX_EDGES];            // per-node {src, w-bits}, 12.8 MB
__device__ int    g_counts[MAX_NODES];
__device__ int    g_offsets[MAX_NODES];
__device__ int    g_cursor[MAX_NODES];
__device__ int    g_total;
__device__ int    g_idx_is32;

// ---------------------------------------------------------------------------
// K1: fused prep: detect idx dtype + zero counts + convert ego -> fp16.
// dtype rule: int64 indices < 1e5 have zero high word; any nonzero high word
// in 64 samples => buffer is int32 pairs.
// ---------------------------------------------------------------------------
__global__ void prep_kernel(const float4* __restrict__ ego4,
                            const unsigned long long* __restrict__ ei,
                            int n_nodes, int n4, int n_samples) {
    int i = blockIdx.x * blockDim.x + threadIdx.x;
    if (i == 0) {
        int saw_high = 0;
        for (int s = 0; s < n_samples; s++)
            if (ei[s] >> 32) { saw_high = 1; break; }
        g_idx_is32 = saw_high;
        g_total = 0;
    }
    if (i < n_nodes) g_counts[i] = 0;
    if (i < n4) {
        float4 v = ego4[i];
        __half2 h01 = __floats2half2_rn(v.x, v.y);
        __half2 h23 = __floats2half2_rn(v.z, v.w);
        g_egoh[i] = make_uint2(*reinterpret_cast<unsigned*>(&h01),
                               *reinterpret_cast<unsigned*>(&h23));
    }
}

// K2: histogram of dst degrees — 4 edges/thread for atomic MLP
__global__ void count_kernel(const void* __restrict__ ei, int n_edges, int n_nodes) {
    int base = (blockIdx.x * blockDim.x + threadIdx.x) * 4;
    int is32 = g_idx_is32;
    #pragma unroll
    for (int j = 0; j < 4; j++) {
        int e = base + j;
        if (e >= n_edges) break;
        long long dst = is32 ? (long long)((const int*)ei)[e]
                             : ((const long long*)ei)[e];
        if ((unsigned long long)dst < (unsigned long long)n_nodes)
            atomicAdd(&g_counts[dst], 1);       // no return use -> REDG
    }
}

// K3: per-node segment offsets. Block-local scan + one global atomicAdd per
// block for the base (segment disjointness is order-independent).
__global__ void offsets_kernel(int n_nodes) {
    __shared__ int warp_sums[32];
    __shared__ int block_base;
    int i = blockIdx.x * 1024 + threadIdx.x;
    int lane = threadIdx.x & 31, wid = threadIdx.x >> 5;

    int c = (i < n_nodes) ? g_counts[i] : 0;
    int x = c;
    #pragma unroll
    for (int d = 1; d < 32; d <<= 1) {
        int y = __shfl_up_sync(0xFFFFFFFFu, x, d);
        if (lane >= d) x += y;
    }
    if (lane == 31) warp_sums[wid] = x;
    __syncthreads();
    if (wid == 0) {
        int s = warp_sums[lane];
        #pragma unroll
        for (int d = 1; d < 32; d <<= 1) {
            int y = __shfl_up_sync(0xFFFFFFFFu, s, d);
            if (lane >= d) s += y;
        }
        warp_sums[lane] = s;
        if (lane == 31) block_base = atomicAdd(&g_total, s);
    }
    __syncthreads();
    int warp_base = (wid > 0) ? warp_sums[wid - 1] : 0;
    int excl = block_base + warp_base + (x - c);
    if (i < n_nodes) { g_offsets[i] = excl; g_cursor[i] = excl; }
}

// K4: scatter edges into per-node segments — 4 edges/thread: 4 independent
// load -> atomic(318cyc) -> store chains in flight instead of 1.
__global__ void fill_kernel(const void* __restrict__ ei,
                            const float* __restrict__ ew,
                            int n_edges, int n_nodes) {
    int base = (blockIdx.x * blockDim.x + threadIdx.x) * 4;
    int is32 = g_idx_is32;

    long long dst[4], src[4];
    float w[4];
    int valid[4];
    #pragma unroll
    for (int j = 0; j < 4; j++) {
        int e = base + j;
        valid[j] = (e < n_edges);
        if (valid[j]) {
            if (is32) {
                dst[j] = (long long)((const int*)ei)[e];
                src[j] = (long long)((const int*)ei)[n_edges + e];
            } else {
                dst[j] = ((const long long*)ei)[e];
                src[j] = ((const long long*)ei)[n_edges + e];
            }
            w[j] = ew[e];
            if ((unsigned long long)dst[j] >= (unsigned long long)n_nodes ||
                (unsigned long long)src[j] >= (unsigned long long)n_nodes)
                valid[j] = 0;
        }
    }
    int pos[4];
    #pragma unroll
    for (int j = 0; j < 4; j++)
        if (valid[j]) pos[j] = atomicAdd(&g_cursor[dst[j]], 1);
    #pragma unroll
    for (int j = 0; j < 4; j++)
        if (valid[j] && pos[j] < MAX_EDGES)
            g_edges[pos[j]] = make_uint2((unsigned)src[j], __float_as_uint(w[j]));
}

// ---------------------------------------------------------------------------
// K5: gather-aggregate (fp16 messages, fp32 acc + fp32 self row), bf16 hi/lo
// split emit. One warp per node, full occupancy (this phase is latency-bound:
// R13 showed it must NOT be fused down to 16 warps/SM).
// ---------------------------------------------------------------------------
__device__ __forceinline__ unsigned pack_bf16(float a, float b) {
    __nv_bfloat162 t = __floats2bfloat162_rn(a, b);
    return *reinterpret_cast<unsigned*>(&t);
}

__device__ __forceinline__ void acc_h(float4& acc, uint2 q, float w) {
    float2 f01 = __half22float2(*reinterpret_cast<__half2*>(&q.x));
    float2 f23 = __half22float2(*reinterpret_cast<__half2*>(&q.y));
    acc.x += f01.x * w; acc.y += f01.y * w;
    acc.z += f23.x * w; acc.w += f23.y * w;
}

__global__ __launch_bounds__(256)
void aggregate_kernel(const float4* __restrict__ ego4, int n_nodes) {
    int warp = (blockIdx.x * blockDim.x + threadIdx.x) >> 5;
    int lane = threadIdx.x & 31;
    if (warp >= n_nodes) return;

    int off = g_offsets[warp];
    int deg = g_counts[warp];

    float4 acc = ego4[(long)warp * 32 + lane];   // self row, fp32

    int e = 0;
    for (; e + 4 <= deg; e += 4) {
        uint2 p0 = g_edges[off + e + 0];
        uint2 p1 = g_edges[off + e + 1];
        uint2 p2 = g_edges[off + e + 2];
        uint2 p3 = g_edges[off + e + 3];
        uint2 q0 = g_egoh[(long)p0.x * 32 + lane];
        uint2 q1 = g_egoh[(long)p1.x * 32 + lane];
        uint2 q2 = g_egoh[(long)p2.x * 32 + lane];
        uint2 q3 = g_egoh[(long)p3.x * 32 + lane];
        acc_h(acc, q0, __uint_as_float(p0.y));
        acc_h(acc, q1, __uint_as_float(p1.y));
        acc_h(acc, q2, __uint_as_float(p2.y));
        acc_h(acc, q3, __uint_as_float(p3.y));
    }
    for (; e < deg; e++) {
        uint2 p = g_edges[off + e];
        uint2 q = g_egoh[(long)p.x * 32 + lane];
        acc_h(acc, q, __uint_as_float(p.y));
    }

    __nv_bfloat162 h01 = __floats2bfloat162_rn(acc.x, acc.y);
    __nv_bfloat162 h23 = __floats2bfloat162_rn(acc.z, acc.w);
    float lx = acc.x - __bfloat162float(h01.x);
    float ly = acc.y - __bfloat162float(h01.y);
    float lz = acc.z - __bfloat162float(h23.x);
    float lw = acc.w - __bfloat162float(h23.y);

    g_xhi[(long)warp * 32 + lane] =
        make_uint2(*reinterpret_cast<unsigned*>(&h01), *reinterpret_cast<unsigned*>(&h23));
    g_xlo[(long)warp * 32 + lane] = make_uint2(pack_bf16(lx, ly), pack_bf16(lz, lw));
}

// ---------------------------------------------------------------------------
// K6: persistent bf16 tensor GEMM: out = LeakyReLU(x @ W^T + b), 3-pass hi/lo.
// W fragment table staged ONCE per CTA; grid-stride over 64-row x tiles.
// ---------------------------------------------------------------------------
#define XS_STRIDE 68   // u32 (k-pair) stride: bank = 4*row + pair -> conflict-free

__device__ __forceinline__ void mma_bf16(float* c, const unsigned* a,
                                         unsigned b0, unsigned b1) {
    asm volatile(
        "mma.sync.aligned.m16n8k16.row.col.f32.bf16.bf16.f32 "
        "{%0,%1,%2,%3}, {%4,%5,%6,%7}, {%8,%9}, {%0,%1,%2,%3};"
        : "+f"(c[0]), "+f"(c[1]), "+f"(c[2]), "+f"(c[3])
        : "r"(a[0]), "r"(a[1]), "r"(a[2]), "r"(a[3]), "r"(b0), "r"(b1));
}

__global__ __launch_bounds__(256, 2)
void gemm_bf16_kernel(const float* __restrict__ W,
                      const float* __restrict__ b,
                      float* __restrict__ out, int n_nodes, int n_tiles) {
    extern __shared__ unsigned smu[];
    uint4*    wf    = reinterpret_cast<uint4*>(smu);       // [16 t][8 kt][32 l]
    unsigned* xs_hi = smu + 16384;                         // [64][XS_STRIDE]
    unsigned* xs_lo = xs_hi + 64 * XS_STRIDE;
    float*    bs    = reinterpret_cast<float*>(xs_lo + 64 * XS_STRIDE);  // [128]

    int tid = threadIdx.x;
    int lane = tid & 31, wid = tid >> 5;

    for (int e = tid; e < 4096; e += 256) {
        int t = e >> 8, kt = (e >> 5) & 7, l = e & 31;
        int n = t * 8 + (l >> 2);
        int k0 = kt * 16 + (l & 3) * 2;
        const float* wr = W + n * D + k0;
        float f0 = wr[0], f1 = wr[1], f8 = wr[8], f9 = wr[9];
        __nv_bfloat162 h01 = __floats2bfloat162_rn(f0, f1);
        __nv_bfloat162 h89 = __floats2bfloat162_rn(f8, f9);
        unsigned hi01 = *reinterpret_cast<unsigned*>(&h01);
        unsigned hi89 = *reinterpret_cast<unsigned*>(&h89);
        unsigned lo01 = pack_bf16(f0 - __bfloat162float(h01.x), f1 - __bfloat162float(h01.y));
        unsigned lo89 = pack_bf16(f8 - __bfloat162float(h89.x), f9 - __bfloat162float(h89.y));
        wf[e] = make_uint4(hi01, hi89, lo01, lo89);
    }
    if (tid < D) bs[tid] = b[tid];

    int m0 = (wid >> 1) * 16;
    int nh = (wid & 1) * 8;
    int g = lane >> 2, tig = lane & 3;

    for (int tile = blockIdx.x; tile < n_tiles; tile += gridDim.x) {
        int row0 = tile * 64;
        __syncthreads();

        for (int idx = tid; idx < 64 * 32; idx += 256) {
            int r = idx >> 5, l = idx & 31;
            int row = row0 + r;
            uint2 vh = make_uint2(0u, 0u), vl = make_uint2(0u, 0u);
            if (row < n_nodes) {
                vh = g_xhi[(long)row * 32 + l];
                vl = g_xlo[(long)row * 32 + l];
            }
            xs_hi[r * XS_STRIDE + 2 * l]     = vh.x;
            xs_hi[r * XS_STRIDE + 2 * l + 1] = vh.y;
            xs_lo[r * XS_STRIDE + 2 * l]     = vl.x;
            xs_lo[r * XS_STRIDE + 2 * l + 1] = vl.y;
        }
        __syncthreads();

        float acc[8][4];
        #pragma unroll
        for (int t = 0; t < 8; t++)
            #pragma unroll
            for (int i = 0; i < 4; i++) acc[t][i] = 0.f;

        #pragma unroll
        for (int kt = 0; kt < 8; kt++) {
            int base = kt * 8 + tig;
            unsigned ahi[4], alo[4];
            ahi[0] = xs_hi[(m0 + g) * XS_STRIDE + base];
            ahi[1] = xs_hi[(m0 + g + 8) * XS_STRIDE + base];
            ahi[2] = xs_hi[(m0 + g) * XS_STRIDE + base + 4];
            ahi[3] = xs_hi[(m0 + g + 8) * XS_STRIDE + base + 4];
            alo[0] = xs_lo[(m0 + g) * XS_STRIDE + base];
            alo[1] = xs_lo[(m0 + g + 8) * XS_STRIDE + base];
            alo[2] = xs_lo[(m0 + g) * XS_STRIDE + base + 4];
            alo[3] = xs_lo[(m0 + g + 8) * XS_STRIDE + base + 4];

            #pragma unroll
            for (int t = 0; t < 8; t++) {
                uint4 w4 = wf[((nh + t) * 8 + kt) * 32 + lane];
                mma_bf16(acc[t], ahi, w4.x, w4.y);   // hi*hi
                mma_bf16(acc[t], ahi, w4.z, w4.w);   // hi*lo
                mma_bf16(acc[t], alo, w4.x, w4.y);   // lo*hi
            }
        }

        int r0 = row0 + m0 + g;
        #pragma unroll
        for (int t = 0; t < 8; t++) {
            int col = (nh + t) * 8 + 2 * tig;
            float bb0 = bs[col], bb1 = bs[col + 1];
            float v0 = acc[t][0] + bb0, v1 = acc[t][1] + bb1;
            float v2 = acc[t][2] + bb0, v3 = acc[t][3] + bb1;
            v0 = v0 > 0.f ? v0 : 0.01f * v0;
            v1 = v1 > 0.f ? v1 : 0.01f * v1;
            v2 = v2 > 0.f ? v2 : 0.01f * v2;
            v3 = v3 > 0.f ? v3 : 0.01f * v3;
            if (r0 < n_nodes)
                *reinterpret_cast<float2*>(out + (long)r0 * D + col) = make_float2(v0, v1);
            if (r0 + 8 < n_nodes)
                *reinterpret_cast<float2*>(out + (long)(r0 + 8) * D + col) = make_float2(v2, v3);
        }
    }
}

// ---------------------------------------------------------------------------
extern "C" void kernel_launch(void* const* d_in, const int* in_sizes, int n_in,
                              void* d_out, int out_size) {
    const float* ego = (const float*)d_in[0];
    const void*  ei  = d_in[1];
    const float* ew  = (const float*)d_in[2];
    const float* W   = (const float*)d_in[3];
    const float* b   = (const float*)d_in[4];
    float*       out = (float*)d_out;

    int n_nodes = in_sizes[0] / D;
    int n_edges = in_sizes[2];
    if (n_edges > MAX_EDGES) n_edges = MAX_EDGES;

    int n4 = n_nodes * 32;
    int n_samples = n_edges < 64 ? n_edges : 64;

    prep_kernel<<<(n4 + 255) / 256, 256>>>((const float4*)ego,
                                           (const unsigned long long*)ei,
                                           n_nodes, n4, n_samples);

    int e4 = (n_edges + 3) / 4;
    count_kernel<<<(e4 + 255) / 256, 256>>>(ei, n_edges, n_nodes);
    offsets_kernel<<<(n_nodes + 1023) / 1024, 1024>>>(n_nodes);
    fill_kernel<<<(e4 + 255) / 256, 256>>>(ei, ew, n_edges, n_nodes);

    aggregate_kernel<<<(n_nodes + 7) / 8, 256>>>((const float4*)ego, n_nodes);

    int n_tiles = (n_nodes + 63) / 64;
    int gblocks = 296 < n_tiles ? 296 : n_tiles;
    size_t smem = (16384 + 2 * 64 * XS_STRIDE) * sizeof(unsigned) + D * sizeof(float);
    cudaFuncSetAttribute(gemm_bf16_kernel,
                         cudaFuncAttributeMaxDynamicSharedMemorySize, (int)smem);
    gemm_bf16_kernel<<<gblocks, 256, smem>>>(W, b, out, n_nodes, n_tiles);
}

// round 15
// speedup vs baseline: 1.3388x; 1.0021x over previous
#include <cuda_runtime.h>
#include <cuda_bf16.h>
#include <cuda_fp16.h>
#include <cstdint>

#define D 128
#define MAX_NODES 100000
#define MAX_EDGES 1600000

// ---- scratch (__device__ globals; no allocs allowed) ----
__device__ uint2  g_xhi[MAX_NODES * 32];         // x hi bf16 pairs, 25.6 MB
__device__ uint2  g_xlo[MAX_NODES * 32];         // x lo bf16 pairs, 25.6 MB
__device__ uint2  g_egoh[MAX_NODES * 32];        // ego as fp16, 25.6 MB
__device__ uint2  g_edges[MAX_EDGES];            // per-node {src, w-bits}, 12.8 MB
__device__ int    g_counts[MAX_NODES];
__device__ int    g_offsets[MAX_NODES];
__device__ int    g_cursor[MAX_NODES];
__device__ int    g_total;
__device__ int    g_idx_is32;

// ---------------------------------------------------------------------------
// K1: fused prep: detect idx dtype + zero counts + convert ego -> fp16.
// dtype rule: int64 indices < 1e5 have zero high word; any nonzero high word
// in 64 samples => buffer is int32 pairs.
// ---------------------------------------------------------------------------
__global__ void prep_kernel(const float4* __restrict__ ego4,
                            const unsigned long long* __restrict__ ei,
                            int n_nodes, int n4, int n_samples) {
    int i = blockIdx.x * blockDim.x + threadIdx.x;
    if (i == 0) {
        int saw_high = 0;
        for (int s = 0; s < n_samples; s++)
            if (ei[s] >> 32) { saw_high = 1; break; }
        g_idx_is32 = saw_high;
        g_total = 0;
    }
    if (i < n_nodes) g_counts[i] = 0;
    if (i < n4) {
        float4 v = ego4[i];
        __half2 h01 = __floats2half2_rn(v.x, v.y);
        __half2 h23 = __floats2half2_rn(v.z, v.w);
        g_egoh[i] = make_uint2(*reinterpret_cast<unsigned*>(&h01),
                               *reinterpret_cast<unsigned*>(&h23));
    }
}

// K2: histogram of dst degrees — 8 edges/thread, phased (loads then REDG),
// generous reg budget so all chains stay live.
__global__ __launch_bounds__(256, 2)
void count_kernel(const void* __restrict__ ei, int n_edges, int n_nodes) {
    int base = (blockIdx.x * blockDim.x + threadIdx.x) * 8;
    int is32 = g_idx_is32;
    int dst[8];
    #pragma unroll
    for (int j = 0; j < 8; j++) {
        int e = base + j;
        dst[j] = -1;
        if (e < n_edges) {
            long long d = is32 ? (long long)((const int*)ei)[e]
                               : ((const long long*)ei)[e];
            if ((unsigned long long)d < (unsigned long long)n_nodes) dst[j] = (int)d;
        }
    }
    #pragma unroll
    for (int j = 0; j < 8; j++)
        if (dst[j] >= 0) atomicAdd(&g_counts[dst[j]], 1);   // no return -> REDG
}

// K3: per-node segment offsets. Block-local scan + one global atomicAdd per
// block for the base (segment disjointness is order-independent).
__global__ void offsets_kernel(int n_nodes) {
    __shared__ int warp_sums[32];
    __shared__ int block_base;
    int i = blockIdx.x * 1024 + threadIdx.x;
    int lane = threadIdx.x & 31, wid = threadIdx.x >> 5;

    int c = (i < n_nodes) ? g_counts[i] : 0;
    int x = c;
    #pragma unroll
    for (int d = 1; d < 32; d <<= 1) {
        int y = __shfl_up_sync(0xFFFFFFFFu, x, d);
        if (lane >= d) x += y;
    }
    if (lane == 31) warp_sums[wid] = x;
    __syncthreads();
    if (wid == 0) {
        int s = warp_sums[lane];
        #pragma unroll
        for (int d = 1; d < 32; d <<= 1) {
            int y = __shfl_up_sync(0xFFFFFFFFu, s, d);
            if (lane >= d) s += y;
        }
        warp_sums[lane] = s;
        if (lane == 31) block_base = atomicAdd(&g_total, s);
    }
    __syncthreads();
    int warp_base = (wid > 0) ? warp_sums[wid - 1] : 0;
    int excl = block_base + warp_base + (x - c);
    if (i < n_nodes) { g_offsets[i] = excl; g_cursor[i] = excl; }
}

// K4: scatter edges into per-node segments — 8 edges/thread in explicit
// phases (loads -> atomics -> stores). __launch_bounds__(256,2) gives a
// 128-reg budget so ptxas keeps all 8 ATOMG chains live (R14: at 32 regs the
// 4-chain version was serialized, issue=6%).
__global__ __launch_bounds__(256, 2)
void fill_kernel(const void* __restrict__ ei,
                 const float* __restrict__ ew,
                 int n_edges, int n_nodes) {
    int base = (blockIdx.x * blockDim.x + threadIdx.x) * 8;
    int is32 = g_idx_is32;

    int dst[8], src[8];
    float w[8];
    #pragma unroll
    for (int j = 0; j < 8; j++) {
        int e = base + j;
        dst[j] = -1; src[j] = 0; w[j] = 0.f;
        if (e < n_edges) {
            long long d, s;
            if (is32) {
                d = (long long)((const int*)ei)[e];
                s = (long long)((const int*)ei)[n_edges + e];
            } else {
                d = ((const long long*)ei)[e];
                s = ((const long long*)ei)[n_edges + e];
            }
            w[j] = ew[e];
            if ((unsigned long long)d < (unsigned long long)n_nodes &&
                (unsigned long long)s < (unsigned long long)n_nodes) {
                dst[j] = (int)d; src[j] = (int)s;
            }
        }
    }
    int pos[8];
    #pragma unroll
    for (int j = 0; j < 8; j++)
        pos[j] = (dst[j] >= 0) ? atomicAdd(&g_cursor[dst[j]], 1) : -1;
    #pragma unroll
    for (int j = 0; j < 8; j++)
        if (pos[j] >= 0 && pos[j] < MAX_EDGES)
            g_edges[pos[j]] = make_uint2((unsigned)src[j], __float_as_uint(w[j]));
}

// ---------------------------------------------------------------------------
// K5: gather-aggregate (fp16 messages, fp32 acc + fp32 self row), bf16 hi/lo
// split emit. One warp per node, full occupancy (R13: do NOT fuse this down).
// ---------------------------------------------------------------------------
__device__ __forceinline__ unsigned pack_bf16(float a, float b) {
    __nv_bfloat162 t = __floats2bfloat162_rn(a, b);
    return *reinterpret_cast<unsigned*>(&t);
}

__device__ __forceinline__ void acc_h(float4& acc, uint2 q, float w) {
    float2 f01 = __half22float2(*reinterpret_cast<__half2*>(&q.x));
    float2 f23 = __half22float2(*reinterpret_cast<__half2*>(&q.y));
    acc.x += f01.x * w; acc.y += f01.y * w;
    acc.z += f23.x * w; acc.w += f23.y * w;
}

__global__ __launch_bounds__(256)
void aggregate_kernel(const float4* __restrict__ ego4, int n_nodes) {
    int warp = (blockIdx.x * blockDim.x + threadIdx.x) >> 5;
    int lane = threadIdx.x & 31;
    if (warp >= n_nodes) return;

    int off = g_offsets[warp];
    int deg = g_counts[warp];

    float4 acc = ego4[(long)warp * 32 + lane];   // self row, fp32

    int e = 0;
    for (; e + 4 <= deg; e += 4) {
        uint2 p0 = g_edges[off + e + 0];
        uint2 p1 = g_edges[off + e + 1];
        uint2 p2 = g_edges[off + e + 2];
        uint2 p3 = g_edges[off + e + 3];
        uint2 q0 = g_egoh[(long)p0.x * 32 + lane];
        uint2 q1 = g_egoh[(long)p1.x * 32 + lane];
        uint2 q2 = g_egoh[(long)p2.x * 32 + lane];
        uint2 q3 = g_egoh[(long)p3.x * 32 + lane];
        acc_h(acc, q0, __uint_as_float(p0.y));
        acc_h(acc, q1, __uint_as_float(p1.y));
        acc_h(acc, q2, __uint_as_float(p2.y));
        acc_h(acc, q3, __uint_as_float(p3.y));
    }
    for (; e < deg; e++) {
        uint2 p = g_edges[off + e];
        uint2 q = g_egoh[(long)p.x * 32 + lane];
        acc_h(acc, q, __uint_as_float(p.y));
    }

    __nv_bfloat162 h01 = __floats2bfloat162_rn(acc.x, acc.y);
    __nv_bfloat162 h23 = __floats2bfloat162_rn(acc.z, acc.w);
    float lx = acc.x - __bfloat162float(h01.x);
    float ly = acc.y - __bfloat162float(h01.y);
    float lz = acc.z - __bfloat162float(h23.x);
    float lw = acc.w - __bfloat162float(h23.y);

    g_xhi[(long)warp * 32 + lane] =
        make_uint2(*reinterpret_cast<unsigned*>(&h01), *reinterpret_cast<unsigned*>(&h23));
    g_xlo[(long)warp * 32 + lane] = make_uint2(pack_bf16(lx, ly), pack_bf16(lz, lw));
}

// ---------------------------------------------------------------------------
// K6: persistent bf16 tensor GEMM: out = LeakyReLU(x @ W^T + b), 3-pass hi/lo.
// W fragment table staged ONCE per CTA; grid-stride over 64-row x tiles.
// ---------------------------------------------------------------------------
#define XS_STRIDE 68   // u32 (k-pair) stride: bank = 4*row + pair -> conflict-free

__device__ __forceinline__ void mma_bf16(float* c, const unsigned* a,
                                         unsigned b0, unsigned b1) {
    asm volatile(
        "mma.sync.aligned.m16n8k16.row.col.f32.bf16.bf16.f32 "
        "{%0,%1,%2,%3}, {%4,%5,%6,%7}, {%8,%9}, {%0,%1,%2,%3};"
        : "+f"(c[0]), "+f"(c[1]), "+f"(c[2]), "+f"(c[3])
        : "r"(a[0]), "r"(a[1]), "r"(a[2]), "r"(a[3]), "r"(b0), "r"(b1));
}

__global__ __launch_bounds__(256, 2)
void gemm_bf16_kernel(const float* __restrict__ W,
                      const float* __restrict__ b,
                      float* __restrict__ out, int n_nodes, int n_tiles) {
    extern __shared__ unsigned smu[];
    uint4*    wf    = reinterpret_cast<uint4*>(smu);       // [16 t][8 kt][32 l]
    unsigned* xs_hi = smu + 16384;                         // [64][XS_STRIDE]
    unsigned* xs_lo = xs_hi + 64 * XS_STRIDE;
    float*    bs    = reinterpret_cast<float*>(xs_lo + 64 * XS_STRIDE);  // [128]

    int tid = threadIdx.x;
    int lane = tid & 31, wid = tid >> 5;

    for (int e = tid; e < 4096; e += 256) {
        int t = e >> 8, kt = (e >> 5) & 7, l = e & 31;
        int n = t * 8 + (l >> 2);
        int k0 = kt * 16 + (l & 3) * 2;
        const float* wr = W + n * D + k0;
        float f0 = wr[0], f1 = wr[1], f8 = wr[8], f9 = wr[9];
        __nv_bfloat162 h01 = __floats2bfloat162_rn(f0, f1);
        __nv_bfloat162 h89 = __floats2bfloat162_rn(f8, f9);
        unsigned hi01 = *reinterpret_cast<unsigned*>(&h01);
        unsigned hi89 = *reinterpret_cast<unsigned*>(&h89);
        unsigned lo01 = pack_bf16(f0 - __bfloat162float(h01.x), f1 - __bfloat162float(h01.y));
        unsigned lo89 = pack_bf16(f8 - __bfloat162float(h89.x), f9 - __bfloat162float(h89.y));
        wf[e] = make_uint4(hi01, hi89, lo01, lo89);
    }
    if (tid < D) bs[tid] = b[tid];

    int m0 = (wid >> 1) * 16;
    int nh = (wid & 1) * 8;
    int g = lane >> 2, tig = lane & 3;

    for (int tile = blockIdx.x; tile < n_tiles; tile += gridDim.x) {
        int row0 = tile * 64;
        __syncthreads();

        for (int idx = tid; idx < 64 * 32; idx += 256) {
            int r = idx >> 5, l = idx & 31;
            int row = row0 + r;
            uint2 vh = make_uint2(0u, 0u), vl = make_uint2(0u, 0u);
            if (row < n_nodes) {
                vh = g_xhi[(long)row * 32 + l];
                vl = g_xlo[(long)row * 32 + l];
            }
            xs_hi[r * XS_STRIDE + 2 * l]     = vh.x;
            xs_hi[r * XS_STRIDE + 2 * l + 1] = vh.y;
            xs_lo[r * XS_STRIDE + 2 * l]     = vl.x;
            xs_lo[r * XS_STRIDE + 2 * l + 1] = vl.y;
        }
        __syncthreads();

        float acc[8][4];
        #pragma unroll
        for (int t = 0; t < 8; t++)
            #pragma unroll
            for (int i = 0; i < 4; i++) acc[t][i] = 0.f;

        #pragma unroll
        for (int kt = 0; kt < 8; kt++) {
            int base = kt * 8 + tig;
            unsigned ahi[4], alo[4];
            ahi[0] = xs_hi[(m0 + g) * XS_STRIDE + base];
            ahi[1] = xs_hi[(m0 + g + 8) * XS_STRIDE + base];
            ahi[2] = xs_hi[(m0 + g) * XS_STRIDE + base + 4];
            ahi[3] = xs_hi[(m0 + g + 8) * XS_STRIDE + base + 4];
            alo[0] = xs_lo[(m0 + g) * XS_STRIDE + base];
            alo[1] = xs_lo[(m0 + g + 8) * XS_STRIDE + base];
            alo[2] = xs_lo[(m0 + g) * XS_STRIDE + base + 4];
            alo[3] = xs_lo[(m0 + g + 8) * XS_STRIDE + base + 4];

            #pragma unroll
            for (int t = 0; t < 8; t++) {
                uint4 w4 = wf[((nh + t) * 8 + kt) * 32 + lane];
                mma_bf16(acc[t], ahi, w4.x, w4.y);   // hi*hi
                mma_bf16(acc[t], ahi, w4.z, w4.w);   // hi*lo
                mma_bf16(acc[t], alo, w4.x, w4.y);   // lo*hi
            }
        }

        int r0 = row0 + m0 + g;
        #pragma unroll
        for (int t = 0; t < 8; t++) {
            int col = (nh + t) * 8 + 2 * tig;
            float bb0 = bs[col], bb1 = bs[col + 1];
            float v0 = acc[t][0] + bb0, v1 = acc[t][1] + bb1;
            float v2 = acc[t][2] + bb0, v3 = acc[t][3] + bb1;
            v0 = v0 > 0.f ? v0 : 0.01f * v0;
            v1 = v1 > 0.f ? v1 : 0.01f * v1;
            v2 = v2 > 0.f ? v2 : 0.01f * v2;
            v3 = v3 > 0.f ? v3 : 0.01f * v3;
            if (r0 < n_nodes)
                *reinterpret_cast<float2*>(out + (long)r0 * D + col) = make_float2(v0, v1);
            if (r0 + 8 < n_nodes)
                *reinterpret_cast<float2*>(out + (long)(r0 + 8) * D + col) = make_float2(v2, v3);
        }
    }
}

// ---------------------------------------------------------------------------
extern "C" void kernel_launch(void* const* d_in, const int* in_sizes, int n_in,
                              void* d_out, int out_size) {
    const float* ego = (const float*)d_in[0];
    const void*  ei  = d_in[1];
    const float* ew  = (const float*)d_in[2];
    const float* W   = (const float*)d_in[3];
    const float* b   = (const float*)d_in[4];
    float*       out = (float*)d_out;

    int n_nodes = in_sizes[0] / D;
    int n_edges = in_sizes[2];
    if (n_edges > MAX_EDGES) n_edges = MAX_EDGES;

    int n4 = n_nodes * 32;
    int n_samples = n_edges < 64 ? n_edges : 64;

    prep_kernel<<<(n4 + 255) / 256, 256>>>((const float4*)ego,
                                           (const unsigned long long*)ei,
                                           n_nodes, n4, n_samples);

    int e8 = (n_edges + 7) / 8;
    count_kernel<<<(e8 + 255) / 256, 256>>>(ei, n_edges, n_nodes);
    offsets_kernel<<<(n_nodes + 1023) / 1024, 1024>>>(n_nodes);
    fill_kernel<<<(e8 + 255) / 256, 256>>>(ei, ew, n_edges, n_nodes);

    aggregate_kernel<<<(n_nodes + 7) / 8, 256>>>((const float4*)ego, n_nodes);

    int n_tiles = (n_nodes + 63) / 64;
    int gblocks = 296 < n_tiles ? 296 : n_tiles;
    size_t smem = (16384 + 2 * 64 * XS_STRIDE) * sizeof(unsigned) + D * sizeof(float);
    cudaFuncSetAttribute(gemm_bf16_kernel,
                         cudaFuncAttributeMaxDynamicSharedMemorySize, (int)smem);
    gemm_bf16_kernel<<<gblocks, 256, smem>>>(W, b, out, n_nodes, n_tiles);
}